// round 2
// baseline (speedup 1.0000x reference)
#include <cuda_runtime.h>

#define CC 173
#define LL 400
#define BB 64

// Static scratch (no allocations allowed in kernel_launch).
__device__ float g_pooled[BB * CC * 32 * 10];   // [B][55360] pooled features
__device__ float g_hpart[CC * BB * 128];        // [173][64][128] split-K partials

// ---------------------------------------------------------------------------
// Fused per-(b,c) tower: conv1(1->16,k9,p4)+BN+ReLU -> conv2(16->32,k7,p3)+BN+ReLU
// -> maxpool(40) -> g_pooled
// ---------------------------------------------------------------------------
__global__ __launch_bounds__(160, 1) void tower_kernel(
    const float* __restrict__ x,
    const float* __restrict__ w1, const float* __restrict__ b1,
    const float* __restrict__ g1, const float* __restrict__ be1,
    const float* __restrict__ m1, const float* __restrict__ v1,
    const float* __restrict__ w2, const float* __restrict__ b2,
    const float* __restrict__ g2, const float* __restrict__ be2,
    const float* __restrict__ m2, const float* __restrict__ v2)
{
    __shared__ float xs[408];            // x with 4-wide zero halos
    __shared__ float y1s[16][408];       // y1, idx = pos+3, zero halos
    __shared__ float w1s[144];
    __shared__ float A1s[16], B1s[16];
    __shared__ float w2s[32][113];       // padded stride 113 -> conflict-free f2 lanes
    __shared__ float A2s[32], B2s[32];

    const int c = blockIdx.x;
    const int b = blockIdx.y;
    const int tid = threadIdx.x;

    // ---- stage 0: loads ----
    for (int i = tid; i < 408; i += 160) {
        int p = i - 4;
        xs[i] = (p >= 0 && p < LL) ? x[(b * CC + c) * LL + p] : 0.f;
    }
    for (int i = tid; i < 144; i += 160) w1s[i] = w1[c * 144 + i];
    for (int i = tid; i < 3584; i += 160) {
        w2s[i / 112][i % 112] = w2[c * 3584 + i];
    }
    if (tid < 16) {
        int cf = c * 16 + tid;
        float inv = g1[cf] * rsqrtf(v1[cf] + 1e-5f);
        A1s[tid] = inv;
        B1s[tid] = fmaf(b1[cf] - m1[cf], inv, be1[cf]);
    } else if (tid >= 32 && tid < 64) {
        int f = tid - 32;
        int cf = c * 32 + f;
        float inv = g2[cf] * rsqrtf(v2[cf] + 1e-5f);
        A2s[f] = inv;
        B2s[f] = fmaf(b2[cf] - m2[cf], inv, be2[cf]);
    }
    __syncthreads();

    // ---- stage 1: conv1 + BN + ReLU into y1s (with zero halos) ----
    for (int i = tid; i < 16 * 408; i += 160) {
        int f = i / 408, idx = i % 408;
        int p = idx - 3;                      // output position -3..404
        float val = 0.f;
        if (p >= 0 && p < LL) {
            float s = 0.f;
            const float* wf = &w1s[f * 9];
            const float* xp = &xs[p];         // xs[p+k] == x(p-4+k)
            #pragma unroll
            for (int k = 0; k < 9; k++) s = fmaf(xp[k], wf[k], s);
            val = fmaxf(fmaf(s, A1s[f], B1s[f]), 0.f);
        }
        y1s[f][idx] = val;
    }
    __syncthreads();

    // ---- stage 2: conv2 + BN + ReLU + maxpool(40) ----
    // item -> (win = item/32, f2 = item%32): warp-uniform win => broadcast y1 LDS
    for (int item = tid; item < 320; item += 160) {
        const int win = item >> 5;
        const int f2  = item & 31;
        float acc[40];
        #pragma unroll
        for (int l = 0; l < 40; l++) acc[l] = 0.f;

        const float* w2f = &w2s[f2][0];
        for (int f1 = 0; f1 < 16; f1++) {
            const float wk0 = w2f[f1 * 7 + 0];
            const float wk1 = w2f[f1 * 7 + 1];
            const float wk2 = w2f[f1 * 7 + 2];
            const float wk3 = w2f[f1 * 7 + 3];
            const float wk4 = w2f[f1 * 7 + 4];
            const float wk5 = w2f[f1 * 7 + 5];
            const float wk6 = w2f[f1 * 7 + 6];
            const float* yr = &y1s[f1][win * 40];   // yr[l+k], k=0..6
            float s0 = yr[0], s1 = yr[1], s2 = yr[2], s3 = yr[3],
                  s4 = yr[4], s5 = yr[5], s6 = yr[6];
            #pragma unroll
            for (int l = 0; l < 40; l++) {
                float a = acc[l];
                a = fmaf(s0, wk0, a);
                a = fmaf(s1, wk1, a);
                a = fmaf(s2, wk2, a);
                a = fmaf(s3, wk3, a);
                a = fmaf(s4, wk4, a);
                a = fmaf(s5, wk5, a);
                a = fmaf(s6, wk6, a);
                acc[l] = a;
                s0 = s1; s1 = s2; s2 = s3; s3 = s4; s4 = s5; s5 = s6;
                s6 = yr[l + 7];   // idx <= win*40+46 <= 406, halo-zeroed
            }
        }
        const float sA = A2s[f2], sB = B2s[f2];
        float mx = -3.402823466e38f;
        #pragma unroll
        for (int l = 0; l < 40; l++) mx = fmaxf(mx, fmaf(acc[l], sA, sB));
        mx = fmaxf(mx, 0.f);
        g_pooled[b * 55360 + (c * 32 + f2) * 10 + win] = mx;
    }
}

// ---------------------------------------------------------------------------
// MLP layer 1, deterministic split-K: block = channel (K-chunk of 320)
// computes partial [64 x 128] into g_hpart[blk].
// ---------------------------------------------------------------------------
__global__ __launch_bounds__(256, 2) void mlp1_kernel(const float* __restrict__ wc1)
{
    __shared__ float As[64][17];
    __shared__ float Bs[128][17];
    const int blk  = blockIdx.x;          // 0..172
    const int base = blk * 320;
    const int t  = threadIdx.x;
    const int tb = t & 15;                // 16 b-groups x 4 rows
    const int tj = t >> 4;                // 16 j-groups x 8 cols

    float acc[4][8];
    #pragma unroll
    for (int i = 0; i < 4; i++)
        #pragma unroll
        for (int j = 0; j < 8; j++) acc[i][j] = 0.f;

    for (int k0 = 0; k0 < 320; k0 += 16) {
        for (int idx = t; idx < 64 * 16; idx += 256) {
            int bb = idx >> 4, kk = idx & 15;
            As[bb][kk] = g_pooled[bb * 55360 + base + k0 + kk];
        }
        for (int idx = t; idx < 128 * 16; idx += 256) {
            int j = idx >> 4, kk = idx & 15;
            Bs[j][kk] = wc1[j * 55360 + base + k0 + kk];
        }
        __syncthreads();
        #pragma unroll
        for (int kk = 0; kk < 16; kk++) {
            float a[4], w[8];
            #pragma unroll
            for (int i = 0; i < 4; i++) a[i] = As[tb * 4 + i][kk];
            #pragma unroll
            for (int j = 0; j < 8; j++) w[j] = Bs[tj * 8 + j][kk];
            #pragma unroll
            for (int i = 0; i < 4; i++)
                #pragma unroll
                for (int j = 0; j < 8; j++) acc[i][j] = fmaf(a[i], w[j], acc[i][j]);
        }
        __syncthreads();
    }
    #pragma unroll
    for (int i = 0; i < 4; i++)
        #pragma unroll
        for (int j = 0; j < 8; j++)
            g_hpart[blk * 8192 + (tb * 4 + i) * 128 + (tj * 8 + j)] = acc[i][j];
}

// ---------------------------------------------------------------------------
// Reduce split-K partials, ReLU, second linear, write out[b].
// ---------------------------------------------------------------------------
__global__ __launch_bounds__(128) void mlp2_kernel(
    const float* __restrict__ bc1, const float* __restrict__ wc2,
    const float* __restrict__ bc2, float* __restrict__ out)
{
    const int b = blockIdx.x;
    const int j = threadIdx.x;
    float s = 0.f;
    for (int sb = 0; sb < CC; sb++) s += g_hpart[sb * 8192 + b * 128 + j];
    float h = fmaxf(s + bc1[j], 0.f);
    float p = h * wc2[j];
    __shared__ float red[128];
    red[j] = p;
    __syncthreads();
    for (int o = 64; o > 0; o >>= 1) {
        if (j < o) red[j] += red[j + o];
        __syncthreads();
    }
    if (j == 0) out[b] = red[0] + bc2[0];
}

// ---------------------------------------------------------------------------
extern "C" void kernel_launch(void* const* d_in, const int* in_sizes, int n_in,
                              void* d_out, int out_size)
{
    const float* x    = (const float*)d_in[0];
    const float* w1   = (const float*)d_in[1];
    const float* b1   = (const float*)d_in[2];
    const float* g1   = (const float*)d_in[3];
    const float* be1  = (const float*)d_in[4];
    const float* m1   = (const float*)d_in[5];
    const float* v1   = (const float*)d_in[6];
    const float* w2   = (const float*)d_in[7];
    const float* b2   = (const float*)d_in[8];
    const float* g2   = (const float*)d_in[9];
    const float* be2  = (const float*)d_in[10];
    const float* m2   = (const float*)d_in[11];
    const float* v2   = (const float*)d_in[12];
    const float* wc1  = (const float*)d_in[13];
    const float* bc1  = (const float*)d_in[14];
    const float* wc2  = (const float*)d_in[15];
    const float* bc2  = (const float*)d_in[16];
    float* out = (float*)d_out;

    dim3 gridA(CC, BB);
    tower_kernel<<<gridA, 160>>>(x, w1, b1, g1, be1, m1, v1,
                                 w2, b2, g2, be2, m2, v2);
    mlp1_kernel<<<CC, 256>>>(wc1);
    mlp2_kernel<<<BB, 128>>>(bc1, wc2, bc2, out);
}

// round 3
// speedup vs baseline: 1.3034x; 1.3034x over previous
#include <cuda_runtime.h>

#define CC 173
#define LL 400
#define BB 64
#define NSPLIT 346   // mlp1 split-K blocks (2 per channel, K-chunk 160)

// Static scratch (no allocations allowed).
__device__ float g_pooled[BB * CC * 32 * 10];      // [B][55360] pooled features
__device__ float g_hpart[NSPLIT * BB * 128];       // split-K partials

// f32x2 packed helpers (sm_103a FFMA2 — PTX-only pattern)
#define PACK2(d, lo, hi) \
    asm("mov.b64 %0, {%1, %2};" : "=l"(d) : "f"(lo), "f"(hi))
#define UNPACK2(lo, hi, v) \
    asm("mov.b64 {%0, %1}, %2;" : "=f"(lo), "=f"(hi) : "l"(v))
#define FMA2(d, a, b, c) \
    asm("fma.rn.f32x2 %0, %1, %2, %3;" : "=l"(d) : "l"(a), "l"(b), "l"(c))

// ---------------------------------------------------------------------------
// Fused per-(b,c) tower: conv1(1->16,k9,p4)+BN+ReLU -> conv2(16->32,k7,p3)+BN+ReLU
// -> maxpool(40) -> g_pooled
// ---------------------------------------------------------------------------
__global__ __launch_bounds__(160, 1) void tower_kernel(
    const float* __restrict__ x,
    const float* __restrict__ w1, const float* __restrict__ b1,
    const float* __restrict__ g1, const float* __restrict__ be1,
    const float* __restrict__ m1, const float* __restrict__ v1,
    const float* __restrict__ w2, const float* __restrict__ b2,
    const float* __restrict__ g2, const float* __restrict__ be2,
    const float* __restrict__ m2, const float* __restrict__ v2)
{
    __shared__ float xs[408];            // x with 4-wide zero halos
    __shared__ float y1s[16][408];       // y1, idx = pos+3, zero halos
    __shared__ float w1s[144];
    __shared__ float A1s[16], B1s[16];
    __shared__ float w2s[32][113];       // stride 113 (17 mod 32) -> conflict-free f2 lanes
    __shared__ float A2s[32], B2s[32];

    const int c = blockIdx.x;
    const int b = blockIdx.y;
    const int tid = threadIdx.x;

    // ---- stage 0: loads ----
    for (int i = tid; i < 408; i += 160) {
        int p = i - 4;
        xs[i] = (p >= 0 && p < LL) ? x[(b * CC + c) * LL + p] : 0.f;
    }
    for (int i = tid; i < 144; i += 160) w1s[i] = w1[c * 144 + i];
    for (int i = tid; i < 3584; i += 160) {
        w2s[i / 112][i % 112] = w2[c * 3584 + i];
    }
    if (tid < 16) {
        int cf = c * 16 + tid;
        float inv = g1[cf] * rsqrtf(v1[cf] + 1e-5f);
        A1s[tid] = inv;
        B1s[tid] = fmaf(b1[cf] - m1[cf], inv, be1[cf]);
    } else if (tid >= 32 && tid < 64) {
        int f = tid - 32;
        int cf = c * 32 + f;
        float inv = g2[cf] * rsqrtf(v2[cf] + 1e-5f);
        A2s[f] = inv;
        B2s[f] = fmaf(b2[cf] - m2[cf], inv, be2[cf]);
    }
    __syncthreads();

    // ---- stage 1: conv1 + BN + ReLU into y1s (with zero halos) ----
    for (int i = tid; i < 16 * 408; i += 160) {
        int f = i / 408, idx = i % 408;
        int p = idx - 3;                      // output position -3..404
        float val = 0.f;
        if (p >= 0 && p < LL) {
            float s = 0.f;
            const float* wf = &w1s[f * 9];
            const float* xp = &xs[p];         // xs[p+k] == x(p-4+k)
            #pragma unroll
            for (int k = 0; k < 9; k++) s = fmaf(xp[k], wf[k], s);
            val = fmaxf(fmaf(s, A1s[f], B1s[f]), 0.f);
        }
        y1s[f][idx] = val;
    }
    __syncthreads();

    // ---- stage 2: conv2 + BN + ReLU + maxpool(40), packed f32x2 ----
    // item -> (win = item/32, f2 = item%32): warp-uniform win/f1/l => broadcast y1 LDS.
    // Outputs (l, l+20) packed together; inputs are pairs (yr[i], yr[i+20]).
    for (int item = tid; item < 320; item += 160) {
        const int win = item >> 5;
        const int f2  = item & 31;

        unsigned long long acc2[20];
        #pragma unroll
        for (int l = 0; l < 20; l++) acc2[l] = 0ull;

        const float* w2f = &w2s[f2][0];
        for (int f1 = 0; f1 < 16; f1++) {
            unsigned long long wp[7];
            #pragma unroll
            for (int k = 0; k < 7; k++) {
                float wk = w2f[f1 * 7 + k];
                PACK2(wp[k], wk, wk);
            }
            const float* yr = &y1s[f1][win * 40];
            unsigned long long P0, P1, P2, P3, P4, P5, P6;
            PACK2(P0, yr[0], yr[20]);
            PACK2(P1, yr[1], yr[21]);
            PACK2(P2, yr[2], yr[22]);
            PACK2(P3, yr[3], yr[23]);
            PACK2(P4, yr[4], yr[24]);
            PACK2(P5, yr[5], yr[25]);
            PACK2(P6, yr[6], yr[26]);
            #pragma unroll
            for (int l = 0; l < 20; l++) {
                unsigned long long a = acc2[l];
                FMA2(a, P0, wp[0], a);
                FMA2(a, P1, wp[1], a);
                FMA2(a, P2, wp[2], a);
                FMA2(a, P3, wp[3], a);
                FMA2(a, P4, wp[4], a);
                FMA2(a, P5, wp[5], a);
                FMA2(a, P6, wp[6], a);
                acc2[l] = a;
                P0 = P1; P1 = P2; P2 = P3; P3 = P4; P4 = P5; P5 = P6;
                // next pair: (yr[l+7], yr[l+27]); max idx win*40+46 <= 406 (halo-zeroed)
                PACK2(P6, yr[l + 7], yr[l + 27]);
            }
        }
        const float sA = A2s[f2], sB = B2s[f2];
        float mx = 0.f;   // relu'd values are >= 0, so 0 is a valid identity
        #pragma unroll
        for (int l = 0; l < 20; l++) {
            float lo, hi;
            UNPACK2(lo, hi, acc2[l]);
            mx = fmaxf(mx, fmaf(lo, sA, sB));
            mx = fmaxf(mx, fmaf(hi, sA, sB));
        }
        g_pooled[b * 55360 + (c * 32 + f2) * 10 + win] = mx;
    }
}

// ---------------------------------------------------------------------------
// MLP layer 1, deterministic split-K: block = 160-wide K-chunk (2 per channel).
// Computes partial [64 x 128] into g_hpart[blk].
// ---------------------------------------------------------------------------
__global__ __launch_bounds__(256, 2) void mlp1_kernel(const float* __restrict__ wc1)
{
    __shared__ float As[64][17];
    __shared__ float Bs[128][17];
    const int blk  = blockIdx.x;          // 0..345
    const int base = blk * 160;
    const int t  = threadIdx.x;
    const int tb = t & 15;                // 16 b-groups x 4 rows
    const int tj = t >> 4;                // 16 j-groups x 8 cols

    float acc[4][8];
    #pragma unroll
    for (int i = 0; i < 4; i++)
        #pragma unroll
        for (int j = 0; j < 8; j++) acc[i][j] = 0.f;

    for (int k0 = 0; k0 < 160; k0 += 16) {
        for (int idx = t; idx < 64 * 16; idx += 256) {
            int bb = idx >> 4, kk = idx & 15;
            As[bb][kk] = g_pooled[bb * 55360 + base + k0 + kk];
        }
        for (int idx = t; idx < 128 * 16; idx += 256) {
            int j = idx >> 4, kk = idx & 15;
            Bs[j][kk] = wc1[j * 55360 + base + k0 + kk];
        }
        __syncthreads();
        #pragma unroll
        for (int kk = 0; kk < 16; kk++) {
            float a[4], w[8];
            #pragma unroll
            for (int i = 0; i < 4; i++) a[i] = As[tb * 4 + i][kk];
            #pragma unroll
            for (int j = 0; j < 8; j++) w[j] = Bs[tj * 8 + j][kk];
            #pragma unroll
            for (int i = 0; i < 4; i++)
                #pragma unroll
                for (int j = 0; j < 8; j++) acc[i][j] = fmaf(a[i], w[j], acc[i][j]);
        }
        __syncthreads();
    }
    #pragma unroll
    for (int i = 0; i < 4; i++)
        #pragma unroll
        for (int j = 0; j < 8; j++)
            g_hpart[blk * 8192 + (tb * 4 + i) * 128 + (tj * 8 + j)] = acc[i][j];
}

// ---------------------------------------------------------------------------
// Reduce split-K partials, ReLU, second linear, write out[b].
// ---------------------------------------------------------------------------
__global__ __launch_bounds__(128) void mlp2_kernel(
    const float* __restrict__ bc1, const float* __restrict__ wc2,
    const float* __restrict__ bc2, float* __restrict__ out)
{
    const int b = blockIdx.x;
    const int j = threadIdx.x;
    float s = 0.f;
    for (int sb = 0; sb < NSPLIT; sb++) s += g_hpart[sb * 8192 + b * 128 + j];
    float h = fmaxf(s + bc1[j], 0.f);
    float p = h * wc2[j];
    __shared__ float red[128];
    red[j] = p;
    __syncthreads();
    for (int o = 64; o > 0; o >>= 1) {
        if (j < o) red[j] += red[j + o];
        __syncthreads();
    }
    if (j == 0) out[b] = red[0] + bc2[0];
}

// ---------------------------------------------------------------------------
extern "C" void kernel_launch(void* const* d_in, const int* in_sizes, int n_in,
                              void* d_out, int out_size)
{
    const float* x    = (const float*)d_in[0];
    const float* w1   = (const float*)d_in[1];
    const float* b1   = (const float*)d_in[2];
    const float* g1   = (const float*)d_in[3];
    const float* be1  = (const float*)d_in[4];
    const float* m1   = (const float*)d_in[5];
    const float* v1   = (const float*)d_in[6];
    const float* w2   = (const float*)d_in[7];
    const float* b2   = (const float*)d_in[8];
    const float* g2   = (const float*)d_in[9];
    const float* be2  = (const float*)d_in[10];
    const float* m2   = (const float*)d_in[11];
    const float* v2   = (const float*)d_in[12];
    const float* wc1  = (const float*)d_in[13];
    const float* bc1  = (const float*)d_in[14];
    const float* wc2  = (const float*)d_in[15];
    const float* bc2  = (const float*)d_in[16];
    float* out = (float*)d_out;

    dim3 gridA(CC, BB);
    tower_kernel<<<gridA, 160>>>(x, w1, b1, g1, be1, m1, v1,
                                 w2, b2, g2, be2, m2, v2);
    mlp1_kernel<<<NSPLIT, 256>>>(wc1);
    mlp2_kernel<<<BB, 128>>>(bc1, wc2, bc2, out);
}